// round 11
// baseline (speedup 1.0000x reference)
#include <cuda_runtime.h>
#include <cuda_fp16.h>
#include <cstdint>

// Problem constants (fixed by the dataset)
#define KBITS 8
#define MDIM  1024   // in_features  (GEMM K)
#define NDIM  1024   // out_features
#define TROWS 8192   // B*S

// ---------------------------------------------------------------------------
// Device scratch
// ---------------------------------------------------------------------------
__device__ __half g_xh[TROWS * MDIM];   // 16 MB  fp16(x)
__device__ __half g_w[NDIM * MDIM];     //  2 MB  W^T fp16 [n][m] (k-contig)

__device__ __forceinline__ uint32_t smem_u32(const void* p) {
    uint32_t a;
    asm("{ .reg .u64 t; cvta.to.shared.u64 t, %1; cvt.u32.u64 %0, t; }" : "=r"(a) : "l"(p));
    return a;
}

// ---------------------------------------------------------------------------
// Prep 1: x -> fp16 (16 floats per thread)
// ---------------------------------------------------------------------------
__global__ __launch_bounds__(256)
void split_x_kernel(const float* __restrict__ x) {
    int idx = (blockIdx.x * 256 + threadIdx.x) * 16;
#pragma unroll
    for (int half = 0; half < 2; half++) {
        int o = idx + half * 8;
        float4 v0 = *reinterpret_cast<const float4*>(x + o);
        float4 v1 = *reinterpret_cast<const float4*>(x + o + 4);
        __half h[8];
        h[0] = __float2half_rn(v0.x); h[1] = __float2half_rn(v0.y);
        h[2] = __float2half_rn(v0.z); h[3] = __float2half_rn(v0.w);
        h[4] = __float2half_rn(v1.x); h[5] = __float2half_rn(v1.y);
        h[6] = __float2half_rn(v1.z); h[7] = __float2half_rn(v1.w);
        *reinterpret_cast<uint4*>(g_xh + o) = *reinterpret_cast<uint4*>(h);
    }
}

// ---------------------------------------------------------------------------
// Prep 2 (v2): fold binary*scale -> W, transpose to [n][m], cast fp16.
// Block covers 8 m x 128 n -> grid (8, 128) = 1024 blocks for occupancy.
// ---------------------------------------------------------------------------
__global__ __launch_bounds__(256)
void fold_kernel(const float* __restrict__ binary,
                 const float* __restrict__ scale) {
    __shared__ float tile[8][132];      // [m][n], +4 pad
    const int n0 = blockIdx.x * 128;
    const int m0 = blockIdx.y * 8;
    const int t = threadIdx.x;
    const int nc = (t & 31) * 4;
    const int mr = t >> 5;              // 0..7

    float4 s[KBITS];
#pragma unroll
    for (int k = 0; k < KBITS; k++)
        s[k] = *reinterpret_cast<const float4*>(scale + k * NDIM + n0 + nc);

    {
        int m = m0 + mr;
        float4 acc = make_float4(0.f, 0.f, 0.f, 0.f);
#pragma unroll
        for (int k = 0; k < KBITS; k++) {
            float4 b = *reinterpret_cast<const float4*>(
                binary + (size_t)k * MDIM * NDIM + (size_t)m * NDIM + n0 + nc);
            acc.x += b.x * s[k].x;
            acc.y += b.y * s[k].y;
            acc.z += b.z * s[k].z;
            acc.w += b.w * s[k].w;
        }
        *reinterpret_cast<float4*>(&tile[mr][nc]) = acc;
    }
    __syncthreads();

    // transpose out: thread t < 128 handles n-row t -> 8 halves (16 B)
    if (t < 128) {
        __half h[8];
#pragma unroll
        for (int i = 0; i < 8; i++)
            h[i] = __float2half_rn(tile[i][t]);
        *reinterpret_cast<uint4*>(g_w + (size_t)(n0 + t) * MDIM + m0) =
            *reinterpret_cast<uint4*>(h);
    }
}

// ---------------------------------------------------------------------------
// GEMM: out = xh @ W + bias  via mma.sync fp16 (fp32 accum)
// CTA 128x128, 4 warps (64x64 warp tiles), KC=32, 6-stage cp.async ring,
// 2 chunks per sync region, fragment double-buffering, 2 CTAs/SM.
// SMEM rows 64 B (32 fp16); swizzle: chunk ^= ((row>>1)&3).
// ---------------------------------------------------------------------------
#define BM 128
#define BN 128
#define KC 32
#define STAGES 6
#define TILE_B   (128 * 64)            // one operand tile: 8 KB
#define STAGE_B  (2 * TILE_B)          // A + B = 16 KB
#define SMEM_DYN (STAGES * STAGE_B + 128)   // ~96 KB

__device__ __forceinline__ void cp16(uint32_t saddr, const void* gaddr) {
    asm volatile("cp.async.cg.shared.global [%0], [%1], 16;"
                 :: "r"(saddr), "l"(gaddr) : "memory");
}
__device__ __forceinline__ void cp_commit() {
    asm volatile("cp.async.commit_group;" ::: "memory");
}
__device__ __forceinline__ void ldsm_x4(uint32_t* r, uint32_t addr) {
    asm volatile("ldmatrix.sync.aligned.m8n8.x4.shared.b16 {%0,%1,%2,%3}, [%4];"
                 : "=r"(r[0]), "=r"(r[1]), "=r"(r[2]), "=r"(r[3]) : "r"(addr));
}
__device__ __forceinline__ void mma_f16(float* d, const uint32_t* a, const uint32_t* b) {
    asm volatile("mma.sync.aligned.m16n8k16.row.col.f32.f16.f16.f32 "
                 "{%0,%1,%2,%3}, {%4,%5,%6,%7}, {%8,%9}, {%0,%1,%2,%3};"
                 : "+f"(d[0]), "+f"(d[1]), "+f"(d[2]), "+f"(d[3])
                 : "r"(a[0]), "r"(a[1]), "r"(a[2]), "r"(a[3]), "r"(b[0]), "r"(b[1]));
}

__global__ __launch_bounds__(128, 2)
void gemm_kernel(const float* __restrict__ bias, float* __restrict__ out) {
    extern __shared__ char smem_raw[];
    const uint32_t sbase = (smem_u32(smem_raw) + 127u) & ~127u;

    const int tid = threadIdx.x;
    const int wid = tid >> 5, lid = tid & 31;
    const int warp_m = wid & 1;    // 2 warps along M (64 each)
    const int warp_n = wid >> 1;   // 2 warps along N (64 each)
    const int bx = blockIdx.x, by = blockIdx.y;

    const char* gA = (const char*)(g_xh + (size_t)by * BM * MDIM);
    const char* gB = (const char*)(g_w  + (size_t)bx * BN * MDIM);

    // cp.async mapping: 1024 16B-chunks per stage (512 A + 512 B), 8/thread.
    int ld_part[8], ld_row[8], ld_c[8];
    uint32_t ld_dst[8];
#pragma unroll
    for (int i = 0; i < 8; i++) {
        int id = tid + i * 128;
        ld_part[i] = id >> 9;            // 0 = A, 1 = B
        int rid = id & 511;
        ld_row[i] = rid >> 2;
        ld_c[i] = rid & 3;
        ld_dst[i] = ld_part[i] * TILE_B + ld_row[i] * 64 +
                    ((ld_c[i] ^ ((ld_row[i] >> 1) & 3)) << 4);
    }

    // ldmatrix offsets (kx=0); XOR 0x20 advances within chunk
    uint32_t aoff[4];
#pragma unroll
    for (int f = 0; f < 4; f++) {
        int row = warp_m * 64 + f * 16 + (lid & 15);
        int hl = lid >> 4;
        aoff[f] = row * 64 + ((hl ^ ((row >> 1) & 3)) << 4);
    }
    uint32_t boff[4];
#pragma unroll
    for (int u = 0; u < 4; u++) {
        int nrow = warp_n * 64 + u * 16 + ((lid >> 4) & 1) * 8 + (lid & 7);
        int ch = (lid >> 3) & 1;
        boff[u] = nrow * 64 + ((ch ^ ((nrow >> 1) & 3)) << 4);
    }

    float acc[4][8][4];
#pragma unroll
    for (int i = 0; i < 4; i++)
#pragma unroll
        for (int j = 0; j < 8; j++)
#pragma unroll
            for (int q = 0; q < 4; q++) acc[i][j][q] = 0.f;

    const int NCH = MDIM / KC;     // 32
    const int NSTEP = NCH / 2;     // 16

    auto issue = [&](int stage, int k0) {
        uint32_t sb = sbase + stage * STAGE_B;
#pragma unroll
        for (int i = 0; i < 8; i++) {
            const char* base = ld_part[i] ? gB : gA;
            cp16(sb + ld_dst[i],
                 base + (size_t)ld_row[i] * (MDIM * 2) + k0 * 2 + ld_c[i] * 16);
        }
        cp_commit();
    };

    // fragment buffers (double-buffered across k-steps)
    uint32_t afr[2][4][4], bfr[2][4][4];
    auto load_frag = [&](int c0, int t, int buf) {
        int chunk = c0 + (t >> 1);
        uint32_t kx = (t & 1) << 5;
        uint32_t sA = sbase + (chunk % STAGES) * STAGE_B;
        uint32_t sB = sA + TILE_B;
#pragma unroll
        for (int f = 0; f < 4; f++) ldsm_x4(afr[buf][f], sA + (aoff[f] ^ kx));
#pragma unroll
        for (int u = 0; u < 4; u++) ldsm_x4(bfr[buf][u], sB + (boff[u] ^ kx));
    };

    // prologue: chunks 0..3 in flight
    issue(0, 0);
    issue(1, KC);
    issue(2, 2 * KC);
    issue(3, 3 * KC);

    for (int s = 0; s < NSTEP; s++) {
        const int c0 = 2 * s;
        if (s == NSTEP - 1)
            asm volatile("cp.async.wait_group 0;" ::: "memory");
        else
            asm volatile("cp.async.wait_group 2;" ::: "memory");
        __syncthreads();

        // first fragments, then prefetch next 2 chunks (post-barrier: WAR-safe)
        load_frag(c0, 0, 0);
        if (c0 + 4 < NCH) {
            issue((c0 + 4) % STAGES, (c0 + 4) * KC);
            issue((c0 + 5) % STAGES, (c0 + 5) * KC);
        }

#pragma unroll
        for (int t = 0; t < 4; t++) {
            const int cur = t & 1;
            if (t < 3) load_frag(c0, t + 1, cur ^ 1);
#pragma unroll
            for (int i = 0; i < 4; i++)
#pragma unroll
                for (int j = 0; j < 8; j++)
                    mma_f16(acc[i][j], afr[cur][i], &bfr[cur][j >> 1][(j & 1) * 2]);
        }
    }

    // ---- epilogue: bias + store ----
    const int row0 = by * BM + warp_m * 64;
    const int col0 = bx * BN + warp_n * 64;
    const int lrow = lid >> 2;
    const int lcol = (lid & 3) * 2;
#pragma unroll
    for (int j = 0; j < 8; j++) {
        int c0 = col0 + j * 8 + lcol;
        float2 bv = *reinterpret_cast<const float2*>(bias + c0);
#pragma unroll
        for (int i = 0; i < 4; i++) {
            int r = row0 + i * 16 + lrow;
            float2 o0 = {acc[i][j][0] + bv.x, acc[i][j][1] + bv.y};
            float2 o1 = {acc[i][j][2] + bv.x, acc[i][j][3] + bv.y};
            *reinterpret_cast<float2*>(out + (size_t)r * NDIM + c0) = o0;
            *reinterpret_cast<float2*>(out + (size_t)(r + 8) * NDIM + c0) = o1;
        }
    }
}

// ---------------------------------------------------------------------------
// Launch: prep forked onto two streams, GEMM after join.
// ---------------------------------------------------------------------------
extern "C" void kernel_launch(void* const* d_in, const int* in_sizes, int n_in,
                              void* d_out, int out_size) {
    const float* x      = (const float*)d_in[0];  // [4,2048,1024]
    const float* binary = (const float*)d_in[1];  // [8,1024,1024]
    const float* scale  = (const float*)d_in[2];  // [8,1,1024]
    const float* bias   = (const float*)d_in[3];  // [1024]
    float* out = (float*)d_out;

    static cudaStream_t s2 = nullptr;
    static cudaEvent_t evFork = nullptr, evJoin = nullptr;
    static int init = 0;
    if (!init) {
        cudaStreamCreateWithFlags(&s2, cudaStreamNonBlocking);
        cudaEventCreateWithFlags(&evFork, cudaEventDisableTiming);
        cudaEventCreateWithFlags(&evJoin, cudaEventDisableTiming);
        cudaFuncSetAttribute(gemm_kernel, cudaFuncAttributeMaxDynamicSharedMemorySize, SMEM_DYN);
        init = 1;
    }

    cudaEventRecord(evFork, 0);
    cudaStreamWaitEvent(s2, evFork, 0);
    fold_kernel<<<dim3(NDIM / 128, MDIM / 8), 256, 0, s2>>>(binary, scale);
    split_x_kernel<<<(TROWS * MDIM) / 16 / 256, 256>>>(x);
    cudaEventRecord(evJoin, s2);
    cudaStreamWaitEvent(0, evJoin, 0);

    gemm_kernel<<<dim3(NDIM / BN, TROWS / BM), 128, SMEM_DYN>>>(bias, out);
}

// round 12
// speedup vs baseline: 1.0880x; 1.0880x over previous
#include <cuda_runtime.h>
#include <cuda_fp16.h>
#include <cstdint>

// Problem constants (fixed by the dataset)
#define KBITS 8
#define MDIM  1024   // in_features  (GEMM K)
#define NDIM  1024   // out_features
#define TROWS 8192   // B*S

// ---------------------------------------------------------------------------
// Device scratch
// ---------------------------------------------------------------------------
__device__ __half g_xh[TROWS * MDIM];   // 16 MB  fp16(x)
__device__ __half g_w[NDIM * MDIM];     //  2 MB  W^T fp16 [n][m] (k-contig)

__device__ __forceinline__ uint32_t smem_u32(const void* p) {
    uint32_t a;
    asm("{ .reg .u64 t; cvta.to.shared.u64 t, %1; cvt.u32.u64 %0, t; }" : "=r"(a) : "l"(p));
    return a;
}

// ---------------------------------------------------------------------------
// Prep 1: x -> fp16 (16 floats per thread)
// ---------------------------------------------------------------------------
__global__ __launch_bounds__(256)
void split_x_kernel(const float* __restrict__ x) {
    int idx = (blockIdx.x * 256 + threadIdx.x) * 16;
#pragma unroll
    for (int half = 0; half < 2; half++) {
        int o = idx + half * 8;
        float4 v0 = *reinterpret_cast<const float4*>(x + o);
        float4 v1 = *reinterpret_cast<const float4*>(x + o + 4);
        __half h[8];
        h[0] = __float2half_rn(v0.x); h[1] = __float2half_rn(v0.y);
        h[2] = __float2half_rn(v0.z); h[3] = __float2half_rn(v0.w);
        h[4] = __float2half_rn(v1.x); h[5] = __float2half_rn(v1.y);
        h[6] = __float2half_rn(v1.z); h[7] = __float2half_rn(v1.w);
        *reinterpret_cast<uint4*>(g_xh + o) = *reinterpret_cast<uint4*>(h);
    }
}

// ---------------------------------------------------------------------------
// Prep 2 (v2, validated R11): fold binary*scale -> W, transpose, cast fp16.
// Block covers 8 m x 128 n -> grid (8, 128) = 1024 blocks.
// ---------------------------------------------------------------------------
__global__ __launch_bounds__(256)
void fold_kernel(const float* __restrict__ binary,
                 const float* __restrict__ scale) {
    __shared__ float tile[8][132];      // [m][n], +4 pad
    const int n0 = blockIdx.x * 128;
    const int m0 = blockIdx.y * 8;
    const int t = threadIdx.x;
    const int nc = (t & 31) * 4;
    const int mr = t >> 5;              // 0..7

    float4 s[KBITS];
#pragma unroll
    for (int k = 0; k < KBITS; k++)
        s[k] = *reinterpret_cast<const float4*>(scale + k * NDIM + n0 + nc);

    {
        int m = m0 + mr;
        float4 acc = make_float4(0.f, 0.f, 0.f, 0.f);
#pragma unroll
        for (int k = 0; k < KBITS; k++) {
            float4 b = *reinterpret_cast<const float4*>(
                binary + (size_t)k * MDIM * NDIM + (size_t)m * NDIM + n0 + nc);
            acc.x += b.x * s[k].x;
            acc.y += b.y * s[k].y;
            acc.z += b.z * s[k].z;
            acc.w += b.w * s[k].w;
        }
        *reinterpret_cast<float4*>(&tile[mr][nc]) = acc;
    }
    __syncthreads();

    if (t < 128) {
        __half h[8];
#pragma unroll
        for (int i = 0; i < 8; i++)
            h[i] = __float2half_rn(tile[i][t]);
        *reinterpret_cast<uint4*>(g_w + (size_t)(n0 + t) * MDIM + m0) =
            *reinterpret_cast<uint4*>(h);
    }
}

// ---------------------------------------------------------------------------
// GEMM (exact R10 structure — best measured): out = xh @ W + bias
// CTA 128x128, 4 warps (2x2 grid of 64x64 warp tiles), 128 threads,
// KC=32, 6-stage cp.async pipeline (prefetch distance 4), 2 CTAs/SM.
// SMEM rows 64 B (32 fp16); swizzle: chunk ^= ((row>>1)&3).
// ---------------------------------------------------------------------------
#define BM 128
#define BN 128
#define KC 32
#define STAGES 6
#define TILE_B   (128 * 64)            // one operand tile: 8 KB
#define STAGE_B  (2 * TILE_B)          // A + B = 16 KB
#define SMEM_DYN (STAGES * STAGE_B + 128)   // ~96 KB

__device__ __forceinline__ void cp16(uint32_t saddr, const void* gaddr) {
    asm volatile("cp.async.cg.shared.global [%0], [%1], 16;"
                 :: "r"(saddr), "l"(gaddr) : "memory");
}
__device__ __forceinline__ void cp_commit() {
    asm volatile("cp.async.commit_group;" ::: "memory");
}
__device__ __forceinline__ void ldsm_x4(uint32_t* r, uint32_t addr) {
    asm volatile("ldmatrix.sync.aligned.m8n8.x4.shared.b16 {%0,%1,%2,%3}, [%4];"
                 : "=r"(r[0]), "=r"(r[1]), "=r"(r[2]), "=r"(r[3]) : "r"(addr));
}
__device__ __forceinline__ void mma_f16(float* d, const uint32_t* a, const uint32_t* b) {
    asm volatile("mma.sync.aligned.m16n8k16.row.col.f32.f16.f16.f32 "
                 "{%0,%1,%2,%3}, {%4,%5,%6,%7}, {%8,%9}, {%0,%1,%2,%3};"
                 : "+f"(d[0]), "+f"(d[1]), "+f"(d[2]), "+f"(d[3])
                 : "r"(a[0]), "r"(a[1]), "r"(a[2]), "r"(a[3]), "r"(b[0]), "r"(b[1]));
}

__global__ __launch_bounds__(128, 2)
void gemm_kernel(const float* __restrict__ bias, float* __restrict__ out) {
    extern __shared__ char smem_raw[];
    const uint32_t sbase = (smem_u32(smem_raw) + 127u) & ~127u;

    const int tid = threadIdx.x;
    const int wid = tid >> 5, lid = tid & 31;
    const int warp_m = wid & 1;    // 2 warps along M (64 each)
    const int warp_n = wid >> 1;   // 2 warps along N (64 each)
    const int bx = blockIdx.x, by = blockIdx.y;

    const char* gA = (const char*)(g_xh + (size_t)by * BM * MDIM);
    const char* gB = (const char*)(g_w  + (size_t)bx * BN * MDIM);

    // cp.async mapping: 1024 16B-chunks per stage (512 A + 512 B), 8/thread.
    int ld_part[8], ld_row[8], ld_c[8];
    uint32_t ld_dst[8];
#pragma unroll
    for (int i = 0; i < 8; i++) {
        int id = tid + i * 128;
        ld_part[i] = id >> 9;            // 0 = A, 1 = B
        int rid = id & 511;
        ld_row[i] = rid >> 2;
        ld_c[i] = rid & 3;
        ld_dst[i] = ld_part[i] * TILE_B + ld_row[i] * 64 +
                    ((ld_c[i] ^ ((ld_row[i] >> 1) & 3)) << 4);
    }

    // ldmatrix offsets (ks=0); XOR 0x20 advances to ks=1
    uint32_t aoff[4];
#pragma unroll
    for (int f = 0; f < 4; f++) {
        int row = warp_m * 64 + f * 16 + (lid & 15);
        int hl = lid >> 4;
        aoff[f] = row * 64 + ((hl ^ ((row >> 1) & 3)) << 4);
    }
    uint32_t boff[4];
#pragma unroll
    for (int u = 0; u < 4; u++) {
        int nrow = warp_n * 64 + u * 16 + ((lid >> 4) & 1) * 8 + (lid & 7);
        int ch = (lid >> 3) & 1;
        boff[u] = nrow * 64 + ((ch ^ ((nrow >> 1) & 3)) << 4);
    }

    float acc[4][8][4];
#pragma unroll
    for (int i = 0; i < 4; i++)
#pragma unroll
        for (int j = 0; j < 8; j++)
#pragma unroll
            for (int q = 0; q < 4; q++) acc[i][j][q] = 0.f;

    const int NCH = MDIM / KC;  // 32
    auto issue = [&](int stage, int k0) {
        uint32_t sb = sbase + stage * STAGE_B;
#pragma unroll
        for (int i = 0; i < 8; i++) {
            const char* base = ld_part[i] ? gB : gA;
            cp16(sb + ld_dst[i],
                 base + (size_t)ld_row[i] * (MDIM * 2) + k0 * 2 + ld_c[i] * 16);
        }
        cp_commit();
    };

    // prologue: chunks 0..3 in flight
    issue(0, 0);
    issue(1, KC);
    issue(2, 2 * KC);
    issue(3, 3 * KC);

    for (int c = 0; c < NCH; c++) {
        if (c + 4 < NCH) issue((c + 4) % STAGES, (c + 4) * KC);
        else cp_commit();   // empty group keeps pending count uniform
        asm volatile("cp.async.wait_group 4;" ::: "memory");
        __syncthreads();

        const uint32_t sA = sbase + (c % STAGES) * STAGE_B;
        const uint32_t sB = sA + TILE_B;
#pragma unroll
        for (int ks = 0; ks < 2; ks++) {
            const uint32_t kx = ks << 5;
            uint32_t a[4][4], b[4][4];
#pragma unroll
            for (int f = 0; f < 4; f++) ldsm_x4(a[f], sA + (aoff[f] ^ kx));
#pragma unroll
            for (int u = 0; u < 4; u++) ldsm_x4(b[u], sB + (boff[u] ^ kx));
#pragma unroll
            for (int i = 0; i < 4; i++)
#pragma unroll
                for (int j = 0; j < 8; j++)
                    mma_f16(acc[i][j], a[i], &b[j >> 1][(j & 1) * 2]);
        }
    }

    // ---- epilogue: bias + store ----
    const int row0 = by * BM + warp_m * 64;
    const int col0 = bx * BN + warp_n * 64;
    const int lrow = lid >> 2;
    const int lcol = (lid & 3) * 2;
#pragma unroll
    for (int j = 0; j < 8; j++) {
        int c0 = col0 + j * 8 + lcol;
        float2 bv = *reinterpret_cast<const float2*>(bias + c0);
#pragma unroll
        for (int i = 0; i < 4; i++) {
            int r = row0 + i * 16 + lrow;
            float2 o0 = {acc[i][j][0] + bv.x, acc[i][j][1] + bv.y};
            float2 o1 = {acc[i][j][2] + bv.x, acc[i][j][3] + bv.y};
            *reinterpret_cast<float2*>(out + (size_t)r * NDIM + c0) = o0;
            *reinterpret_cast<float2*>(out + (size_t)(r + 8) * NDIM + c0) = o1;
        }
    }
}

// ---------------------------------------------------------------------------
// Launch: prep forked onto two streams, GEMM after join.
// ---------------------------------------------------------------------------
extern "C" void kernel_launch(void* const* d_in, const int* in_sizes, int n_in,
                              void* d_out, int out_size) {
    const float* x      = (const float*)d_in[0];  // [4,2048,1024]
    const float* binary = (const float*)d_in[1];  // [8,1024,1024]
    const float* scale  = (const float*)d_in[2];  // [8,1,1024]
    const float* bias   = (const float*)d_in[3];  // [1024]
    float* out = (float*)d_out;

    static cudaStream_t s2 = nullptr;
    static cudaEvent_t evFork = nullptr, evJoin = nullptr;
    static int init = 0;
    if (!init) {
        cudaStreamCreateWithFlags(&s2, cudaStreamNonBlocking);
        cudaEventCreateWithFlags(&evFork, cudaEventDisableTiming);
        cudaEventCreateWithFlags(&evJoin, cudaEventDisableTiming);
        cudaFuncSetAttribute(gemm_kernel, cudaFuncAttributeMaxDynamicSharedMemorySize, SMEM_DYN);
        init = 1;
    }

    cudaEventRecord(evFork, 0);
    cudaStreamWaitEvent(s2, evFork, 0);
    fold_kernel<<<dim3(NDIM / 128, MDIM / 8), 256, 0, s2>>>(binary, scale);
    split_x_kernel<<<(TROWS * MDIM) / 16 / 256, 256>>>(x);
    cudaEventRecord(evJoin, s2);
    cudaStreamWaitEvent(0, evJoin, 0);

    gemm_kernel<<<dim3(NDIM / BN, TROWS / BM), 128, SMEM_DYN>>>(bias, out);
}